// round 3
// baseline (speedup 1.0000x reference)
#include <cuda_runtime.h>
#include <math.h>

// FixedRadiusNeighborQuery: for each query point, find up to LIMIT nearest
// points (within RADIUS, same ragged batch segment), sorted by squared
// distance ascending (ties: lower index first).
//
// Inputs (metadata order):
//   d_in[0] points            float32 (N*3)
//   d_in[1] row_splits        int32   (B+1)
//   d_in[2] output_points     float32 (Q*3)
//   d_in[3] output_row_splits int32   (B+1)
// Output: float32, [ idx_as_float (Q*LIMIT) | dist (Q*LIMIT) ]
//
// Numerics deliberately mirror the JAX reference:
//   p2 = (x*x + y*y) + z*z              (rounded squares, left-assoc adds)
//   dot = fma(z,pz, fma(y,py, x*px))    (ascending-k fma chain, as sgemm K=3)
//   d2  = (q2 + p2) - 2*dot             (2*dot exact; that association)
//   d2  = max(d2, 0);  valid = d2 <= 0.09f
//   dist = sqrtf(max(d2, 1e-12f))

#define FRNQ_LIMIT 32
#define FRNQ_TILE  2048
#define FRNQ_WARPS_PER_BLOCK 16
#define FRNQ_THREADS (FRNQ_WARPS_PER_BLOCK * 32)

__global__ __launch_bounds__(FRNQ_THREADS)
void frnq_kernel(const float* __restrict__ points,
                 const int*   __restrict__ row_splits,   int n_rs,
                 const float* __restrict__ qpts,
                 const int*   __restrict__ q_splits,     int n_qs,
                 int Q,
                 float* __restrict__ out_idx,
                 float* __restrict__ out_dist)
{
    __shared__ float4 tile[FRNQ_TILE];

    const int tid  = threadIdx.x;
    const int lane = tid & 31;
    const int warp = tid >> 5;
    const int q    = blockIdx.x * FRNQ_WARPS_PER_BLOCK + warp;
    const bool active_q = (q < Q);

    const float R2  = 0.09f;                        // float(RADIUS*RADIUS)
    const float INF = __int_as_float(0x7f800000);

    // --- batch id of this warp's query (searchsorted right - 1) ---
    int qb = 0;
    {
        int qq = active_q ? q : (Q - 1);
        for (int i = 1; i < n_qs; ++i)
            if (q_splits[i] <= qq) qb = i;
    }
    // --- batch range covered by this block's queries ---
    int qfirst = blockIdx.x * FRNQ_WARPS_PER_BLOCK;
    int qlast  = qfirst + FRNQ_WARPS_PER_BLOCK - 1;
    if (qlast >= Q) qlast = Q - 1;
    int b0 = 0, b1 = 0;
    for (int i = 1; i < n_qs; ++i) {
        if (q_splits[i] <= qfirst) b0 = i;
        if (q_splits[i] <= qlast)  b1 = i;
    }

    // --- query coordinates ---
    float qx = 0.f, qy = 0.f, qz = 0.f, q2 = 0.f;
    if (active_q) {
        qx = qpts[3 * q + 0];
        qy = qpts[3 * q + 1];
        qz = qpts[3 * q + 2];
        q2 = __fadd_rn(__fadd_rn(__fmul_rn(qx, qx), __fmul_rn(qy, qy)),
                       __fmul_rn(qz, qz));
    }

    // --- per-lane sorted candidate list (d2 asc; ties keep earlier idx) ---
    float ld[FRNQ_LIMIT];
    int   li[FRNQ_LIMIT];
    int   n = 0;

    for (int b = b0; b <= b1; ++b) {
        const int ps = row_splits[b];
        const int pe = row_splits[b + 1];
        const bool my_batch = active_q && (qb == b);

        for (int t = ps; t < pe; t += FRNQ_TILE) {
            int cnt = pe - t;
            if (cnt > FRNQ_TILE) cnt = FRNQ_TILE;

            __syncthreads();
            for (int i = tid; i < cnt; i += FRNQ_THREADS) {
                float x = points[3 * (t + i) + 0];
                float y = points[3 * (t + i) + 1];
                float z = points[3 * (t + i) + 2];
                float pp = __fadd_rn(__fadd_rn(__fmul_rn(x, x), __fmul_rn(y, y)),
                                     __fmul_rn(z, z));
                tile[i] = make_float4(x, y, z, pp);
            }
            __syncthreads();

            if (my_batch) {
                for (int k = lane; k < cnt; k += 32) {
                    float4 p = tile[k];
                    float dot = __fmaf_rn(qz, p.z,
                                __fmaf_rn(qy, p.y, __fmul_rn(qx, p.x)));
                    float d2  = __fadd_rn(__fadd_rn(q2, p.w),
                                          -__fmul_rn(2.0f, dot));
                    d2 = fmaxf(d2, 0.0f);
                    if (d2 <= R2) {
                        if (n < FRNQ_LIMIT || d2 < ld[FRNQ_LIMIT - 1]) {
                            int j = (n < FRNQ_LIMIT) ? n : (FRNQ_LIMIT - 1);
                            while (j > 0 && ld[j - 1] > d2) {
                                ld[j] = ld[j - 1];
                                li[j] = li[j - 1];
                                --j;
                            }
                            ld[j] = d2;
                            li[j] = t + k;
                            if (n < FRNQ_LIMIT) ++n;
                        }
                    }
                }
            }
        }
    }

    if (!active_q) return;

    // --- warp merge of 32 sorted lane lists: 32 rounds of argmin(d2, idx) ---
    int   pos = 0;
    float hd  = (n > 0) ? ld[0] : INF;
    int   hi  = (n > 0) ? li[0] : 0x7fffffff;
    float rd  = INF;
    int   ri  = -1;

    #pragma unroll
    for (int r = 0; r < FRNQ_LIMIT; ++r) {
        float bd = hd;
        int   bi = hi;
        int   bl = lane;
        #pragma unroll
        for (int off = 16; off > 0; off >>= 1) {
            float od = __shfl_xor_sync(0xffffffffu, bd, off);
            int   oi = __shfl_xor_sync(0xffffffffu, bi, off);
            int   ol = __shfl_xor_sync(0xffffffffu, bl, off);
            if (od < bd || (od == bd && oi < bi)) { bd = od; bi = oi; bl = ol; }
        }
        if (lane == bl) {
            ++pos;
            if (pos < n) { hd = ld[pos]; hi = li[pos]; }
            else         { hd = INF;     hi = 0x7fffffff; }
        }
        if (r == lane) { rd = bd; ri = bi; }
    }

    const size_t o   = (size_t)q * FRNQ_LIMIT + lane;
    const bool   val = (rd < 1e29f);
    out_idx[o]  = val ? (float)ri : -1.0f;
    out_dist[o] = val ? sqrtf(fmaxf(rd, 1e-12f)) : 0.0f;
}

extern "C" void kernel_launch(void* const* d_in, const int* in_sizes, int n_in,
                              void* d_out, int out_size)
{
    const float* points     = (const float*)d_in[0];
    const int*   row_splits = (const int*)  d_in[1];
    const float* qpts       = (const float*)d_in[2];
    const int*   q_splits   = (const int*)  d_in[3];

    const int n_rs = in_sizes[1];
    const int n_qs = in_sizes[3];
    const int Q    = in_sizes[2] / 3;

    float* out_idx  = (float*)d_out;
    float* out_dist = out_idx + (size_t)Q * FRNQ_LIMIT;

    const int blocks = (Q + FRNQ_WARPS_PER_BLOCK - 1) / FRNQ_WARPS_PER_BLOCK;
    frnq_kernel<<<blocks, FRNQ_THREADS>>>(points, row_splits, n_rs,
                                          qpts, q_splits, n_qs,
                                          Q, out_idx, out_dist);
}

// round 4
// speedup vs baseline: 1.0432x; 1.0432x over previous
#include <cuda_runtime.h>
#include <math.h>

// FixedRadiusNeighborQuery — f32x2-packed brute-force scan.
// One warp per query; block-shared tile of 2048 points in pair-SoA layout:
//   Xs[j] = {x(2j), x(2j+1), y(2j), y(2j+1)}
//   Zs[j] = {z(2j), z(2j+1), p2(2j), p2(2j+1)}
// Inner loop evaluates 2 points per lane-step with packed f32x2 FMA chain.
//
// Numerics mirror the JAX reference exactly:
//   p2 = (x*x + y*y) + z*z
//   dot = fma(z,pz, fma(y,py, x*px))
//   d2  = (q2 + p2) - 2*dot        [via fma(dot,-2, q2+p2): 2*dot exact]
//   valid = max(d2,0) <= 0.09f  (== d2 <= 0.09f)
//   dist = sqrtf(max(max(d2,0), 1e-12))

#define FRNQ_LIMIT 32
#define FRNQ_TILE  2048
#define FRNQ_PAIRS (FRNQ_TILE / 2)
#define FRNQ_WARPS_PER_BLOCK 16
#define FRNQ_THREADS (FRNQ_WARPS_PER_BLOCK * 32)

typedef unsigned long long u64;

__device__ __forceinline__ u64 pk2(float lo, float hi) {
    u64 r; asm("mov.b64 %0, {%1,%2};" : "=l"(r) : "f"(lo), "f"(hi)); return r;
}
__device__ __forceinline__ void upk2(u64 v, float& lo, float& hi) {
    asm("mov.b64 {%0,%1}, %2;" : "=f"(lo), "=f"(hi) : "l"(v));
}
__device__ __forceinline__ u64 mul2(u64 a, u64 b) {
    u64 r; asm("mul.rn.f32x2 %0, %1, %2;" : "=l"(r) : "l"(a), "l"(b)); return r;
}
__device__ __forceinline__ u64 add2(u64 a, u64 b) {
    u64 r; asm("add.rn.f32x2 %0, %1, %2;" : "=l"(r) : "l"(a), "l"(b)); return r;
}
__device__ __forceinline__ u64 fma2(u64 a, u64 b, u64 c) {
    u64 r; asm("fma.rn.f32x2 %0, %1, %2, %3;" : "=l"(r) : "l"(a), "l"(b), "l"(c)); return r;
}

__device__ __forceinline__ void frnq_insert(float d2, int idx,
                                            float* ld, int* li, int& n) {
    if (n < FRNQ_LIMIT || d2 < ld[FRNQ_LIMIT - 1]) {
        int j = (n < FRNQ_LIMIT) ? n : (FRNQ_LIMIT - 1);
        while (j > 0 && ld[j - 1] > d2) {
            ld[j] = ld[j - 1];
            li[j] = li[j - 1];
            --j;
        }
        ld[j] = d2;
        li[j] = idx;
        if (n < FRNQ_LIMIT) ++n;
    }
}

__global__ __launch_bounds__(FRNQ_THREADS)
void frnq_kernel(const float* __restrict__ points,
                 const int*   __restrict__ row_splits,   int n_rs,
                 const float* __restrict__ qpts,
                 const int*   __restrict__ q_splits,     int n_qs,
                 int Q,
                 float* __restrict__ out_idx,
                 float* __restrict__ out_dist)
{
    __shared__ float4 Xs[FRNQ_PAIRS];   // {x0,x1,y0,y1}
    __shared__ float4 Zs[FRNQ_PAIRS];   // {z0,z1,w0,w1}

    const int tid  = threadIdx.x;
    const int lane = tid & 31;
    const int warp = tid >> 5;
    const int q    = blockIdx.x * FRNQ_WARPS_PER_BLOCK + warp;
    const bool active_q = (q < Q);

    const float R2  = 0.09f;
    const float INF = __int_as_float(0x7f800000);

    // --- batch id of this warp's query (searchsorted right - 1) ---
    int qb = 0;
    {
        int qq = active_q ? q : (Q - 1);
        for (int i = 1; i < n_qs; ++i)
            if (q_splits[i] <= qq) qb = i;
    }
    // --- batch range covered by this block's queries ---
    int qfirst = blockIdx.x * FRNQ_WARPS_PER_BLOCK;
    int qlast  = qfirst + FRNQ_WARPS_PER_BLOCK - 1;
    if (qlast >= Q) qlast = Q - 1;
    int b0 = 0, b1 = 0;
    for (int i = 1; i < n_qs; ++i) {
        if (q_splits[i] <= qfirst) b0 = i;
        if (q_splits[i] <= qlast)  b1 = i;
    }

    // --- query coordinates, packed ---
    float qx = 0.f, qy = 0.f, qz = 0.f, q2 = 0.f;
    if (active_q) {
        qx = qpts[3 * q + 0];
        qy = qpts[3 * q + 1];
        qz = qpts[3 * q + 2];
        q2 = __fadd_rn(__fadd_rn(__fmul_rn(qx, qx), __fmul_rn(qy, qy)),
                       __fmul_rn(qz, qz));
    }
    const u64 qx2 = pk2(qx, qx);
    const u64 qy2 = pk2(qy, qy);
    const u64 qz2 = pk2(qz, qz);
    const u64 q22 = pk2(q2, q2);
    const u64 m2  = pk2(-2.0f, -2.0f);

    // --- per-lane sorted candidate list ---
    float ld[FRNQ_LIMIT];
    int   li[FRNQ_LIMIT];
    int   n = 0;

    for (int b = b0; b <= b1; ++b) {
        const int ps = row_splits[b];
        const int pe = row_splits[b + 1];
        const bool my_batch = active_q && (qb == b);

        for (int t = ps; t < pe; t += FRNQ_TILE) {
            int cnt = pe - t;
            if (cnt > FRNQ_TILE) cnt = FRNQ_TILE;
            const int pairs  = cnt >> 1;
            const int pairsT = (cnt + 1) >> 1;   // includes padded tail pair

            __syncthreads();
            for (int i = tid; i < pairs; i += FRNQ_THREADS) {
                const float* p = points + 3 * (t + 2 * i);
                float x0 = p[0], y0 = p[1], z0 = p[2];
                float x1 = p[3], y1 = p[4], z1 = p[5];
                float w0 = __fadd_rn(__fadd_rn(__fmul_rn(x0, x0), __fmul_rn(y0, y0)),
                                     __fmul_rn(z0, z0));
                float w1 = __fadd_rn(__fadd_rn(__fmul_rn(x1, x1), __fmul_rn(y1, y1)),
                                     __fmul_rn(z1, z1));
                Xs[i] = make_float4(x0, x1, y0, y1);
                Zs[i] = make_float4(z0, z1, w0, w1);
            }
            if ((cnt & 1) && tid == 0) {
                const float* p = points + 3 * (t + cnt - 1);
                float x0 = p[0], y0 = p[1], z0 = p[2];
                float w0 = __fadd_rn(__fadd_rn(__fmul_rn(x0, x0), __fmul_rn(y0, y0)),
                                     __fmul_rn(z0, z0));
                // pad hi slot with a far-away dummy (never within radius)
                Xs[pairs] = make_float4(x0, 3e4f, y0, 3e4f);
                Zs[pairs] = make_float4(z0, 3e4f, w0, 2.7e9f);
            }
            __syncthreads();

            if (my_batch) {
                #pragma unroll 4
                for (int j = lane; j < pairsT; j += 32) {
                    float4 xy = Xs[j];
                    float4 zw = Zs[j];
                    u64 x01 = pk2(xy.x, xy.y);
                    u64 y01 = pk2(xy.z, xy.w);
                    u64 z01 = pk2(zw.x, zw.y);
                    u64 w01 = pk2(zw.z, zw.w);

                    u64 dot = mul2(x01, qx2);
                    dot = fma2(y01, qy2, dot);
                    dot = fma2(z01, qz2, dot);
                    u64 s   = add2(w01, q22);     // p2 + q2 (== q2 + p2)
                    u64 d2p = fma2(dot, m2, s);   // (q2+p2) - 2*dot, 1 rounding

                    float d2a, d2b;
                    upk2(d2p, d2a, d2b);

                    if (fminf(d2a, d2b) <= R2) {   // rare path (~0.3/lane/tile)
                        int base = t + (j << 1);
                        if (d2a <= R2)
                            frnq_insert(fmaxf(d2a, 0.0f), base, ld, li, n);
                        if (d2b <= R2)
                            frnq_insert(fmaxf(d2b, 0.0f), base + 1, ld, li, n);
                    }
                }
            }
        }
    }

    if (!active_q) return;

    // --- warp merge of 32 sorted lane lists: 32 rounds of argmin(d2, idx) ---
    int   pos = 0;
    float hd  = (n > 0) ? ld[0] : INF;
    int   hi  = (n > 0) ? li[0] : 0x7fffffff;
    float rd  = INF;
    int   ri  = -1;

    #pragma unroll
    for (int r = 0; r < FRNQ_LIMIT; ++r) {
        float bd = hd;
        int   bi = hi;
        int   bl = lane;
        #pragma unroll
        for (int off = 16; off > 0; off >>= 1) {
            float od = __shfl_xor_sync(0xffffffffu, bd, off);
            int   oi = __shfl_xor_sync(0xffffffffu, bi, off);
            int   ol = __shfl_xor_sync(0xffffffffu, bl, off);
            if (od < bd || (od == bd && oi < bi)) { bd = od; bi = oi; bl = ol; }
        }
        if (lane == bl) {
            ++pos;
            if (pos < n) { hd = ld[pos]; hi = li[pos]; }
            else         { hd = INF;     hi = 0x7fffffff; }
        }
        if (r == lane) { rd = bd; ri = bi; }
    }

    const size_t o   = (size_t)q * FRNQ_LIMIT + lane;
    const bool   val = (rd < 1e29f);
    out_idx[o]  = val ? (float)ri : -1.0f;
    out_dist[o] = val ? sqrtf(fmaxf(rd, 1e-12f)) : 0.0f;
}

extern "C" void kernel_launch(void* const* d_in, const int* in_sizes, int n_in,
                              void* d_out, int out_size)
{
    const float* points     = (const float*)d_in[0];
    const int*   row_splits = (const int*)  d_in[1];
    const float* qpts       = (const float*)d_in[2];
    const int*   q_splits   = (const int*)  d_in[3];

    const int n_rs = in_sizes[1];
    const int n_qs = in_sizes[3];
    const int Q    = in_sizes[2] / 3;

    float* out_idx  = (float*)d_out;
    float* out_dist = out_idx + (size_t)Q * FRNQ_LIMIT;

    const int blocks = (Q + FRNQ_WARPS_PER_BLOCK - 1) / FRNQ_WARPS_PER_BLOCK;
    frnq_kernel<<<blocks, FRNQ_THREADS>>>(points, row_splits, n_rs,
                                          qpts, q_splits, n_qs,
                                          Q, out_idx, out_dist);
}

// round 5
// speedup vs baseline: 1.0680x; 1.0237x over previous
#include <cuda_runtime.h>
#include <math.h>

// FixedRadiusNeighborQuery — f32x2-packed scan, 2 queries per warp.
// Tile layout: per point-pair j, two ulonglong2 at 32B stride:
//   tile[2j]   = { pack(x0,x1), pack(y0,y1) }
//   tile[2j+1] = { pack(z0,z1), pack(p2_0,p2_1) }
// Tile is padded to a multiple of 128 pairs with dummies (0,0,0,1e30) so the
// unroll-4 inner loop needs no bounds checks. Each warp owns queries 2g,2g+1;
// each smem pair read serves 4 distance evaluations.
//
// Numerics mirror the JAX reference exactly:
//   p2 = (x*x + y*y) + z*z
//   dot = fma(z,qz, fma(y,qy, x*qx))
//   d2  = (q2 + p2) - 2*dot       [fma(dot,-2, p2+q2): 2*dot exact, 1 rounding]
//   valid = d2 <= 0.09f ;  dist = sqrtf(max(max(d2,0),1e-12))

#define FRNQ_LIMIT 32
#define FRNQ_TILE  2048
#define FRNQ_PAIRS (FRNQ_TILE / 2)
#define FRNQ_WARPS_PER_BLOCK 8
#define FRNQ_THREADS (FRNQ_WARPS_PER_BLOCK * 32)
#define FRNQ_QPB (FRNQ_WARPS_PER_BLOCK * 2)   // queries per block

typedef unsigned long long u64;

__device__ __forceinline__ u64 pk2(float lo, float hi) {
    u64 r; asm("mov.b64 %0, {%1,%2};" : "=l"(r) : "f"(lo), "f"(hi)); return r;
}
__device__ __forceinline__ void upk2(u64 v, float& lo, float& hi) {
    asm("mov.b64 {%0,%1}, %2;" : "=f"(lo), "=f"(hi) : "l"(v));
}
__device__ __forceinline__ u64 mul2(u64 a, u64 b) {
    u64 r; asm("mul.rn.f32x2 %0, %1, %2;" : "=l"(r) : "l"(a), "l"(b)); return r;
}
__device__ __forceinline__ u64 add2(u64 a, u64 b) {
    u64 r; asm("add.rn.f32x2 %0, %1, %2;" : "=l"(r) : "l"(a), "l"(b)); return r;
}
__device__ __forceinline__ u64 fma2(u64 a, u64 b, u64 c) {
    u64 r; asm("fma.rn.f32x2 %0, %1, %2, %3;" : "=l"(r) : "l"(a), "l"(b), "l"(c)); return r;
}

__device__ __forceinline__ void frnq_insert(float d2, int idx,
                                            float* ld, int* li, int& n) {
    if (n < FRNQ_LIMIT || d2 < ld[FRNQ_LIMIT - 1]) {
        int j = (n < FRNQ_LIMIT) ? n : (FRNQ_LIMIT - 1);
        while (j > 0 && ld[j - 1] > d2) {
            ld[j] = ld[j - 1];
            li[j] = li[j - 1];
            --j;
        }
        ld[j] = d2;
        li[j] = idx;
        if (n < FRNQ_LIMIT) ++n;
    }
}

__global__ __launch_bounds__(FRNQ_THREADS, 3)
void frnq_kernel(const float* __restrict__ points,
                 const int*   __restrict__ row_splits,   int n_rs,
                 const float* __restrict__ qpts,
                 const int*   __restrict__ q_splits,     int n_qs,
                 int Q,
                 float* __restrict__ out_idx,
                 float* __restrict__ out_dist)
{
    __shared__ ulonglong2 tile[FRNQ_PAIRS * 2];

    const int tid  = threadIdx.x;
    const int lane = tid & 31;
    const int warp = tid >> 5;
    const int gw   = blockIdx.x * FRNQ_WARPS_PER_BLOCK + warp;
    const int q0   = 2 * gw;
    const int q1   = 2 * gw + 1;
    const bool a0  = (q0 < Q);
    const bool a1  = (q1 < Q);

    const float R2  = 0.09f;
    const float INF = __int_as_float(0x7f800000);

    // --- batch ids (searchsorted right - 1) ---
    int qb0 = 0, qb1 = 0;
    {
        int s0 = a0 ? q0 : (Q - 1);
        int s1 = a1 ? q1 : (Q - 1);
        for (int i = 1; i < n_qs; ++i) {
            if (q_splits[i] <= s0) qb0 = i;
            if (q_splits[i] <= s1) qb1 = i;
        }
    }
    // --- batch range covered by this block's queries ---
    int qfirst = blockIdx.x * FRNQ_QPB;
    int qlast  = qfirst + FRNQ_QPB - 1;
    if (qlast >= Q) qlast = Q - 1;
    int b0 = 0, b1 = 0;
    for (int i = 1; i < n_qs; ++i) {
        if (q_splits[i] <= qfirst) b0 = i;
        if (q_splits[i] <= qlast)  b1 = i;
    }

    // --- query coordinates, packed f32x2 constants ---
    float qx0 = 0.f, qy0 = 0.f, qz0 = 0.f, qs0 = 0.f;
    float qx1 = 0.f, qy1 = 0.f, qz1 = 0.f, qs1 = 0.f;
    if (a0) {
        qx0 = qpts[3 * q0 + 0]; qy0 = qpts[3 * q0 + 1]; qz0 = qpts[3 * q0 + 2];
        qs0 = __fadd_rn(__fadd_rn(__fmul_rn(qx0, qx0), __fmul_rn(qy0, qy0)),
                        __fmul_rn(qz0, qz0));
    }
    if (a1) {
        qx1 = qpts[3 * q1 + 0]; qy1 = qpts[3 * q1 + 1]; qz1 = qpts[3 * q1 + 2];
        qs1 = __fadd_rn(__fadd_rn(__fmul_rn(qx1, qx1), __fmul_rn(qy1, qy1)),
                        __fmul_rn(qz1, qz1));
    }
    const u64 X0 = pk2(qx0, qx0), Y0 = pk2(qy0, qy0), Z0 = pk2(qz0, qz0), S0 = pk2(qs0, qs0);
    const u64 X1 = pk2(qx1, qx1), Y1 = pk2(qy1, qy1), Z1 = pk2(qz1, qz1), S1 = pk2(qs1, qs1);
    const u64 M2 = pk2(-2.0f, -2.0f);

    // --- per-lane sorted candidate lists (one per query) ---
    float ld[2][FRNQ_LIMIT];
    int   li[2][FRNQ_LIMIT];
    int   nn[2] = {0, 0};

    for (int b = b0; b <= b1; ++b) {
        const int ps = row_splits[b];
        const int pe = row_splits[b + 1];
        const bool my0 = a0 && (qb0 == b);
        const bool my1 = a1 && (qb1 == b);

        for (int t = ps; t < pe; t += FRNQ_TILE) {
            int cnt = pe - t;
            if (cnt > FRNQ_TILE) cnt = FRNQ_TILE;
            const int pairs  = cnt >> 1;
            const int pairsT = (cnt + 1) >> 1;
            const int padded = (pairsT + 127) & ~127;

            __syncthreads();
            for (int i = tid; i < pairs; i += FRNQ_THREADS) {
                const float* p = points + 3 * (t + 2 * i);
                float x0 = p[0], y0 = p[1], z0 = p[2];
                float x1 = p[3], y1 = p[4], z1 = p[5];
                float w0 = __fadd_rn(__fadd_rn(__fmul_rn(x0, x0), __fmul_rn(y0, y0)),
                                     __fmul_rn(z0, z0));
                float w1 = __fadd_rn(__fadd_rn(__fmul_rn(x1, x1), __fmul_rn(y1, y1)),
                                     __fmul_rn(z1, z1));
                ulonglong2 A, B;
                A.x = pk2(x0, x1); A.y = pk2(y0, y1);
                B.x = pk2(z0, z1); B.y = pk2(w0, w1);
                tile[2 * i]     = A;
                tile[2 * i + 1] = B;
            }
            if ((cnt & 1) && tid == 0) {
                const float* p = points + 3 * (t + cnt - 1);
                float x0 = p[0], y0 = p[1], z0 = p[2];
                float w0 = __fadd_rn(__fadd_rn(__fmul_rn(x0, x0), __fmul_rn(y0, y0)),
                                     __fmul_rn(z0, z0));
                ulonglong2 A, B;
                A.x = pk2(x0, 0.f); A.y = pk2(y0, 0.f);
                B.x = pk2(z0, 0.f); B.y = pk2(w0, 1e30f);
                tile[2 * pairs]     = A;
                tile[2 * pairs + 1] = B;
            }
            // pad to a multiple of 128 pairs with far dummies
            for (int i = pairsT + tid; i < padded; i += FRNQ_THREADS) {
                ulonglong2 A, B;
                A.x = 0ull; A.y = 0ull;
                B.x = 0ull; B.y = pk2(1e30f, 1e30f);
                tile[2 * i]     = A;
                tile[2 * i + 1] = B;
            }
            __syncthreads();

            if (my0 || my1) {
                for (int j = lane; j < padded; j += 128) {
                    u64 d0[4], d1[4];
                    float mn = 1e30f;
                    #pragma unroll
                    for (int u = 0; u < 4; ++u) {
                        const int jj = j + u * 32;
                        ulonglong2 A = tile[2 * jj];       // x01, y01
                        ulonglong2 B = tile[2 * jj + 1];   // z01, w01

                        u64 t0 = mul2(A.x, X0);
                        t0 = fma2(A.y, Y0, t0);
                        t0 = fma2(B.x, Z0, t0);
                        d0[u] = fma2(t0, M2, add2(B.y, S0));

                        u64 t1 = mul2(A.x, X1);
                        t1 = fma2(A.y, Y1, t1);
                        t1 = fma2(B.x, Z1, t1);
                        d1[u] = fma2(t1, M2, add2(B.y, S1));

                        float e0, e1, f0, f1;
                        upk2(d0[u], e0, e1);
                        upk2(d1[u], f0, f1);
                        mn = fminf(mn, fminf(fminf(e0, e1), fminf(f0, f1)));
                    }
                    if (mn <= R2) {   // rare path
                        #pragma unroll
                        for (int u = 0; u < 4; ++u) {
                            const int base = t + ((j + u * 32) << 1);
                            float e0, e1, f0, f1;
                            upk2(d0[u], e0, e1);
                            upk2(d1[u], f0, f1);
                            if (my0) {
                                if (e0 <= R2)
                                    frnq_insert(fmaxf(e0, 0.0f), base,     ld[0], li[0], nn[0]);
                                if (e1 <= R2)
                                    frnq_insert(fmaxf(e1, 0.0f), base + 1, ld[0], li[0], nn[0]);
                            }
                            if (my1) {
                                if (f0 <= R2)
                                    frnq_insert(fmaxf(f0, 0.0f), base,     ld[1], li[1], nn[1]);
                                if (f1 <= R2)
                                    frnq_insert(fmaxf(f1, 0.0f), base + 1, ld[1], li[1], nn[1]);
                            }
                        }
                    }
                }
            }
        }
    }

    // --- warp merge: 32 rounds of argmin(d2, idx) per query, early exit ---
    #pragma unroll 1
    for (int s = 0; s < 2; ++s) {
        const int q = 2 * gw + s;
        if (q >= Q) continue;
        const float* mld = ld[s];
        const int*   mli = li[s];
        const int    n   = nn[s];

        int   pos = 0;
        float hd  = (n > 0) ? mld[0] : INF;
        int   hi  = (n > 0) ? mli[0] : 0x7fffffff;
        float rd  = INF;
        int   ri  = -1;

        for (int r = 0; r < FRNQ_LIMIT; ++r) {
            float bd = hd;
            int   bi = hi;
            int   bl = lane;
            #pragma unroll
            for (int off = 16; off > 0; off >>= 1) {
                float od = __shfl_xor_sync(0xffffffffu, bd, off);
                int   oi = __shfl_xor_sync(0xffffffffu, bi, off);
                int   ol = __shfl_xor_sync(0xffffffffu, bl, off);
                if (od < bd || (od == bd && oi < bi)) { bd = od; bi = oi; bl = ol; }
            }
            if (bd == INF) break;   // no candidates left anywhere in the warp
            if (lane == bl) {
                ++pos;
                if (pos < n) { hd = mld[pos]; hi = mli[pos]; }
                else         { hd = INF;      hi = 0x7fffffff; }
            }
            if (r == lane) { rd = bd; ri = bi; }
        }

        const size_t o   = (size_t)q * FRNQ_LIMIT + lane;
        const bool   val = (rd < 1e29f);
        out_idx[o]  = val ? (float)ri : -1.0f;
        out_dist[o] = val ? sqrtf(fmaxf(rd, 1e-12f)) : 0.0f;
    }
}

extern "C" void kernel_launch(void* const* d_in, const int* in_sizes, int n_in,
                              void* d_out, int out_size)
{
    const float* points     = (const float*)d_in[0];
    const int*   row_splits = (const int*)  d_in[1];
    const float* qpts       = (const float*)d_in[2];
    const int*   q_splits   = (const int*)  d_in[3];

    const int n_rs = in_sizes[1];
    const int n_qs = in_sizes[3];
    const int Q    = in_sizes[2] / 3;

    float* out_idx  = (float*)d_out;
    float* out_dist = out_idx + (size_t)Q * FRNQ_LIMIT;

    const int blocks = (Q + FRNQ_QPB - 1) / FRNQ_QPB;
    frnq_kernel<<<blocks, FRNQ_THREADS>>>(points, row_splits, n_rs,
                                          qpts, q_splits, n_qs,
                                          Q, out_idx, out_dist);
}

// round 6
// speedup vs baseline: 1.1130x; 1.0421x over previous
#include <cuda_runtime.h>
#include <math.h>

// FixedRadiusNeighborQuery — f32x2-packed scan, 2 queries per warp,
// geometry tuned for a SINGLE resident wave: 512 blocks x 256 thr at
// occupancy 4 (launch_bounds(256,4), 64 regs, 33KB smem) => all blocks
// co-resident on 148 SMs, no wave-quantization tail.
//
// Tile layout: per point-pair j, two ulonglong2 at 32B stride:
//   tile[2j]   = { pack(x0,x1), pack(y0,y1) }
//   tile[2j+1] = { pack(z0,z1), pack(p2_0,p2_1) }
// padded to a multiple of 128 pairs with far dummies (0,0,0,1e30).
//
// Numerics mirror the JAX reference exactly:
//   p2 = (x*x + y*y) + z*z
//   dot = fma(z,qz, fma(y,qy, x*qx))
//   d2  = (q2 + p2) - 2*dot       [fma(dot,-2, p2+q2): 2*dot exact]
//   valid = d2 <= 0.09f ;  dist = sqrtf(max(max(d2,0),1e-12))

#define FRNQ_LIMIT 32
#define FRNQ_TILE  2048
#define FRNQ_PAIRS (FRNQ_TILE / 2)
#define FRNQ_WARPS_PER_BLOCK 8
#define FRNQ_THREADS (FRNQ_WARPS_PER_BLOCK * 32)
#define FRNQ_QPB (FRNQ_WARPS_PER_BLOCK * 2)   // queries per block

typedef unsigned long long u64;

__device__ __forceinline__ u64 pk2(float lo, float hi) {
    u64 r; asm("mov.b64 %0, {%1,%2};" : "=l"(r) : "f"(lo), "f"(hi)); return r;
}
__device__ __forceinline__ void upk2(u64 v, float& lo, float& hi) {
    asm("mov.b64 {%0,%1}, %2;" : "=f"(lo), "=f"(hi) : "l"(v));
}
__device__ __forceinline__ u64 mul2(u64 a, u64 b) {
    u64 r; asm("mul.rn.f32x2 %0, %1, %2;" : "=l"(r) : "l"(a), "l"(b)); return r;
}
__device__ __forceinline__ u64 add2(u64 a, u64 b) {
    u64 r; asm("add.rn.f32x2 %0, %1, %2;" : "=l"(r) : "l"(a), "l"(b)); return r;
}
__device__ __forceinline__ u64 fma2(u64 a, u64 b, u64 c) {
    u64 r; asm("fma.rn.f32x2 %0, %1, %2, %3;" : "=l"(r) : "l"(a), "l"(b), "l"(c)); return r;
}

__device__ __forceinline__ void frnq_insert(float d2, int idx,
                                            float* ld, int* li, int& n) {
    if (n < FRNQ_LIMIT || d2 < ld[FRNQ_LIMIT - 1]) {
        int j = (n < FRNQ_LIMIT) ? n : (FRNQ_LIMIT - 1);
        while (j > 0 && ld[j - 1] > d2) {
            ld[j] = ld[j - 1];
            li[j] = li[j - 1];
            --j;
        }
        ld[j] = d2;
        li[j] = idx;
        if (n < FRNQ_LIMIT) ++n;
    }
}

__global__ __launch_bounds__(FRNQ_THREADS, 4)
void frnq_kernel(const float* __restrict__ points,
                 const int*   __restrict__ row_splits,   int n_rs,
                 const float* __restrict__ qpts,
                 const int*   __restrict__ q_splits,     int n_qs,
                 int Q,
                 float* __restrict__ out_idx,
                 float* __restrict__ out_dist)
{
    __shared__ ulonglong2 tile[FRNQ_PAIRS * 2];

    const int tid  = threadIdx.x;
    const int lane = tid & 31;
    const int warp = tid >> 5;
    const int gw   = blockIdx.x * FRNQ_WARPS_PER_BLOCK + warp;
    const int q0   = 2 * gw;
    const int q1   = 2 * gw + 1;
    const bool a0  = (q0 < Q);
    const bool a1  = (q1 < Q);

    const float R2  = 0.09f;
    const float INF = __int_as_float(0x7f800000);

    // --- batch ids (searchsorted right - 1) ---
    int qb0 = 0, qb1 = 0;
    {
        int s0 = a0 ? q0 : (Q - 1);
        int s1 = a1 ? q1 : (Q - 1);
        for (int i = 1; i < n_qs; ++i) {
            if (q_splits[i] <= s0) qb0 = i;
            if (q_splits[i] <= s1) qb1 = i;
        }
    }
    // --- batch range covered by this block's queries ---
    int qfirst = blockIdx.x * FRNQ_QPB;
    int qlast  = qfirst + FRNQ_QPB - 1;
    if (qlast >= Q) qlast = Q - 1;
    int b0 = 0, b1 = 0;
    for (int i = 1; i < n_qs; ++i) {
        if (q_splits[i] <= qfirst) b0 = i;
        if (q_splits[i] <= qlast)  b1 = i;
    }

    // --- query coordinates, packed f32x2 constants ---
    float qx0 = 0.f, qy0 = 0.f, qz0 = 0.f, qs0 = 0.f;
    float qx1 = 0.f, qy1 = 0.f, qz1 = 0.f, qs1 = 0.f;
    if (a0) {
        qx0 = qpts[3 * q0 + 0]; qy0 = qpts[3 * q0 + 1]; qz0 = qpts[3 * q0 + 2];
        qs0 = __fadd_rn(__fadd_rn(__fmul_rn(qx0, qx0), __fmul_rn(qy0, qy0)),
                        __fmul_rn(qz0, qz0));
    }
    if (a1) {
        qx1 = qpts[3 * q1 + 0]; qy1 = qpts[3 * q1 + 1]; qz1 = qpts[3 * q1 + 2];
        qs1 = __fadd_rn(__fadd_rn(__fmul_rn(qx1, qx1), __fmul_rn(qy1, qy1)),
                        __fmul_rn(qz1, qz1));
    }
    const u64 X0 = pk2(qx0, qx0), Y0 = pk2(qy0, qy0), Z0 = pk2(qz0, qz0), S0 = pk2(qs0, qs0);
    const u64 X1 = pk2(qx1, qx1), Y1 = pk2(qy1, qy1), Z1 = pk2(qz1, qz1), S1 = pk2(qs1, qs1);
    const u64 M2 = pk2(-2.0f, -2.0f);

    // --- per-lane sorted candidate lists (one per query) ---
    float ld[2][FRNQ_LIMIT];
    int   li[2][FRNQ_LIMIT];
    int   nn[2] = {0, 0};

    for (int b = b0; b <= b1; ++b) {
        const int ps = row_splits[b];
        const int pe = row_splits[b + 1];
        const bool my0 = a0 && (qb0 == b);
        const bool my1 = a1 && (qb1 == b);

        for (int t = ps; t < pe; t += FRNQ_TILE) {
            int cnt = pe - t;
            if (cnt > FRNQ_TILE) cnt = FRNQ_TILE;
            const int pairs  = cnt >> 1;
            const int pairsT = (cnt + 1) >> 1;
            const int padded = (pairsT + 127) & ~127;

            __syncthreads();
            for (int i = tid; i < pairs; i += FRNQ_THREADS) {
                const float* p = points + 3 * (t + 2 * i);
                float x0 = p[0], y0 = p[1], z0 = p[2];
                float x1 = p[3], y1 = p[4], z1 = p[5];
                float w0 = __fadd_rn(__fadd_rn(__fmul_rn(x0, x0), __fmul_rn(y0, y0)),
                                     __fmul_rn(z0, z0));
                float w1 = __fadd_rn(__fadd_rn(__fmul_rn(x1, x1), __fmul_rn(y1, y1)),
                                     __fmul_rn(z1, z1));
                ulonglong2 A, B;
                A.x = pk2(x0, x1); A.y = pk2(y0, y1);
                B.x = pk2(z0, z1); B.y = pk2(w0, w1);
                tile[2 * i]     = A;
                tile[2 * i + 1] = B;
            }
            if ((cnt & 1) && tid == 0) {
                const float* p = points + 3 * (t + cnt - 1);
                float x0 = p[0], y0 = p[1], z0 = p[2];
                float w0 = __fadd_rn(__fadd_rn(__fmul_rn(x0, x0), __fmul_rn(y0, y0)),
                                     __fmul_rn(z0, z0));
                ulonglong2 A, B;
                A.x = pk2(x0, 0.f); A.y = pk2(y0, 0.f);
                B.x = pk2(z0, 0.f); B.y = pk2(w0, 1e30f);
                tile[2 * pairs]     = A;
                tile[2 * pairs + 1] = B;
            }
            for (int i = pairsT + tid; i < padded; i += FRNQ_THREADS) {
                ulonglong2 A, B;
                A.x = 0ull; A.y = 0ull;
                B.x = 0ull; B.y = pk2(1e30f, 1e30f);
                tile[2 * i]     = A;
                tile[2 * i + 1] = B;
            }
            __syncthreads();

            if (my0 || my1) {
                for (int j = lane; j < padded; j += 128) {
                    u64 d0[4], d1[4];
                    float pmn[4];
                    #pragma unroll
                    for (int u = 0; u < 4; ++u) {
                        const int jj = j + u * 32;
                        ulonglong2 A = tile[2 * jj];       // x01, y01
                        ulonglong2 B = tile[2 * jj + 1];   // z01, w01

                        u64 t0 = mul2(A.x, X0);
                        t0 = fma2(A.y, Y0, t0);
                        t0 = fma2(B.x, Z0, t0);
                        d0[u] = fma2(t0, M2, add2(B.y, S0));

                        u64 t1 = mul2(A.x, X1);
                        t1 = fma2(A.y, Y1, t1);
                        t1 = fma2(B.x, Z1, t1);
                        d1[u] = fma2(t1, M2, add2(B.y, S1));

                        float e0, e1, f0, f1;
                        upk2(d0[u], e0, e1);
                        upk2(d1[u], f0, f1);
                        pmn[u] = fminf(fminf(e0, e1), fminf(f0, f1));
                    }
                    // balanced tree over independent partial mins
                    float mn = fminf(fminf(pmn[0], pmn[1]), fminf(pmn[2], pmn[3]));
                    if (mn <= R2) {   // rare path
                        #pragma unroll
                        for (int u = 0; u < 4; ++u) {
                            const int base = t + ((j + u * 32) << 1);
                            float e0, e1, f0, f1;
                            upk2(d0[u], e0, e1);
                            upk2(d1[u], f0, f1);
                            if (my0) {
                                if (e0 <= R2)
                                    frnq_insert(fmaxf(e0, 0.0f), base,     ld[0], li[0], nn[0]);
                                if (e1 <= R2)
                                    frnq_insert(fmaxf(e1, 0.0f), base + 1, ld[0], li[0], nn[0]);
                            }
                            if (my1) {
                                if (f0 <= R2)
                                    frnq_insert(fmaxf(f0, 0.0f), base,     ld[1], li[1], nn[1]);
                                if (f1 <= R2)
                                    frnq_insert(fmaxf(f1, 0.0f), base + 1, ld[1], li[1], nn[1]);
                            }
                        }
                    }
                }
            }
        }
    }

    // --- warp merge: up to 32 rounds of min-reduce + ballot winner pick ---
    #pragma unroll 1
    for (int s = 0; s < 2; ++s) {
        const int q = 2 * gw + s;
        if (q >= Q) continue;
        const float* mld = ld[s];
        const int*   mli = li[s];
        const int    n   = nn[s];

        int   pos = 0;
        float hd  = (n > 0) ? mld[0] : INF;
        int   hi  = (n > 0) ? mli[0] : 0x7fffffff;
        float rd  = INF;
        int   ri  = -1;

        for (int r = 0; r < FRNQ_LIMIT; ++r) {
            // warp-wide min of heads (float only: 1 shfl + 1 fmin per level)
            float bd = hd;
            #pragma unroll
            for (int off = 16; off > 0; off >>= 1)
                bd = fminf(bd, __shfl_xor_sync(0xffffffffu, bd, off));
            if (bd == INF) break;   // no candidates left anywhere in the warp

            unsigned m  = __ballot_sync(0xffffffffu, hd == bd);
            int      wl = __ffs(m) - 1;
            if (__popc(m) > 1) {     // tie on d2: break by lowest point index
                int myi = (hd == bd) ? hi : 0x7fffffff;
                int mi  = myi;
                #pragma unroll
                for (int off = 16; off > 0; off >>= 1)
                    mi = min(mi, __shfl_xor_sync(0xffffffffu, mi, off));
                m  = __ballot_sync(0xffffffffu, myi == mi);
                wl = __ffs(m) - 1;
            }
            int wi = __shfl_sync(0xffffffffu, hi, wl);
            if (r == lane) { rd = bd; ri = wi; }
            if (lane == wl) {
                ++pos;
                if (pos < n) { hd = mld[pos]; hi = mli[pos]; }
                else         { hd = INF;      hi = 0x7fffffff; }
            }
        }

        const size_t o   = (size_t)q * FRNQ_LIMIT + lane;
        const bool   val = (rd < 1e29f);
        out_idx[o]  = val ? (float)ri : -1.0f;
        out_dist[o] = val ? sqrtf(fmaxf(rd, 1e-12f)) : 0.0f;
    }
}

extern "C" void kernel_launch(void* const* d_in, const int* in_sizes, int n_in,
                              void* d_out, int out_size)
{
    const float* points     = (const float*)d_in[0];
    const int*   row_splits = (const int*)  d_in[1];
    const float* qpts       = (const float*)d_in[2];
    const int*   q_splits   = (const int*)  d_in[3];

    const int n_rs = in_sizes[1];
    const int n_qs = in_sizes[3];
    const int Q    = in_sizes[2] / 3;

    float* out_idx  = (float*)d_out;
    float* out_dist = out_idx + (size_t)Q * FRNQ_LIMIT;

    const int blocks = (Q + FRNQ_QPB - 1) / FRNQ_QPB;
    frnq_kernel<<<blocks, FRNQ_THREADS>>>(points, row_splits, n_rs,
                                          qpts, q_splits, n_qs,
                                          Q, out_idx, out_dist);
}

// round 7
// speedup vs baseline: 1.6149x; 1.4510x over previous
#include <cuda_runtime.h>
#include <math.h>

// FixedRadiusNeighborQuery — 1-D x-binned candidate pruning.
//
// Kernel 1 (one block per batch): histogram points by x into 512 bins,
// exclusive-scan, scatter into global scratch as float4{x,y,z,p2} + orig idx,
// bin-sorted. Kernel 2 (one warp per query): scan only the points whose x-bin
// intersects [qx-0.302, qx+0.302] (provably a superset of all points the
// reference accepts), evaluate the exact reference d2 chain, keep top-32.
//
// Numerics identical to the JAX reference:
//   p2 = (x*x + y*y) + z*z
//   dot = fma(qz,pz, fma(qy,py, qx*px))
//   d2  = fma(dot, -2, q2+p2)           [== (q2+p2) - 2*dot, 1 rounding]
//   valid = d2 <= 0.09f ; dist = sqrtf(max(max(d2,0),1e-12))

#define FRNQ_LIMIT 32
#define NBINS 512
#define MAXN  65536
#define MAXB  16
#define XMIN  (-6.5f)
#define INVW  (NBINS / 13.0f)
#define RWIN  0.302f

__device__ float4 g_pts4[MAXN];
__device__ int    g_pidx[MAXN];
__device__ int    g_start[MAXB * (NBINS + 1)];

__device__ __forceinline__ int bin_of(float x) {
    int b = (int)floorf((x - XMIN) * INVW);
    return min(max(b, 0), NBINS - 1);
}

// ---------------- Kernel 1: bin + scatter (grid = B, block = 512) ----------
__global__ __launch_bounds__(512)
void frnq_bin_kernel(const float* __restrict__ points,
                     const int*   __restrict__ row_splits)
{
    __shared__ int hist[NBINS];
    __shared__ int cur[NBINS];
    __shared__ int wsum[16];

    const int b    = blockIdx.x;
    const int ps   = row_splits[b];
    const int pe   = row_splits[b + 1];
    const int tid  = threadIdx.x;
    const int lane = tid & 31;
    const int wid  = tid >> 5;

    hist[tid] = 0;
    __syncthreads();

    for (int i = ps + tid; i < pe; i += 512)
        atomicAdd(&hist[bin_of(points[3 * i])], 1);
    __syncthreads();

    // exclusive scan of 512 counts: warp scans + warp-offset scan
    int v   = hist[tid];
    int inc = v;
    #pragma unroll
    for (int o = 1; o < 32; o <<= 1) {
        int t = __shfl_up_sync(0xffffffffu, inc, o);
        if (lane >= o) inc += t;
    }
    if (lane == 31) wsum[wid] = inc;
    __syncthreads();
    if (wid == 0) {
        int s  = (lane < 16) ? wsum[lane] : 0;
        int si = s;
        #pragma unroll
        for (int o = 1; o < 16; o <<= 1) {
            int t = __shfl_up_sync(0xffffffffu, si, o);
            if (lane >= o) si += t;
        }
        if (lane < 16) wsum[lane] = si - s;   // exclusive warp offsets
    }
    __syncthreads();
    const int excl = inc - v + wsum[wid];
    g_start[b * (NBINS + 1) + tid] = ps + excl;
    if (tid == 0) g_start[b * (NBINS + 1) + NBINS] = pe;
    cur[tid] = excl;
    __syncthreads();

    // scatter (within-bin order nondeterministic; output is order-invariant)
    for (int i = ps + tid; i < pe; i += 512) {
        float x = points[3 * i + 0];
        float y = points[3 * i + 1];
        float z = points[3 * i + 2];
        float p2 = __fadd_rn(__fadd_rn(__fmul_rn(x, x), __fmul_rn(y, y)),
                             __fmul_rn(z, z));
        int bn  = bin_of(x);
        int pos = ps + atomicAdd(&cur[bn], 1);
        g_pts4[pos] = make_float4(x, y, z, p2);
        g_pidx[pos] = i;
    }
}

// ---------------- Kernel 2: query (1 warp per query) -----------------------
#define FRNQ_QWARPS 8
#define FRNQ_QTHREADS (FRNQ_QWARPS * 32)

__device__ __forceinline__ void frnq_insert(float d2, int idx,
                                            float* ld, int* li, int& n) {
    if (n < FRNQ_LIMIT || d2 < ld[FRNQ_LIMIT - 1]) {
        int j = (n < FRNQ_LIMIT) ? n : (FRNQ_LIMIT - 1);
        while (j > 0 && ld[j - 1] > d2) {
            ld[j] = ld[j - 1];
            li[j] = li[j - 1];
            --j;
        }
        ld[j] = d2;
        li[j] = idx;
        if (n < FRNQ_LIMIT) ++n;
    }
}

__global__ __launch_bounds__(FRNQ_QTHREADS)
void frnq_query_kernel(const float* __restrict__ qpts,
                       const int*   __restrict__ q_splits, int n_qs,
                       int Q,
                       float* __restrict__ out_idx,
                       float* __restrict__ out_dist)
{
    const int lane = threadIdx.x & 31;
    const int warp = threadIdx.x >> 5;
    const int q    = blockIdx.x * FRNQ_QWARPS + warp;
    if (q >= Q) return;

    const float R2  = 0.09f;
    const float INF = __int_as_float(0x7f800000);

    // batch id (searchsorted right - 1)
    int qb = 0;
    for (int i = 1; i < n_qs; ++i)
        if (q_splits[i] <= q) qb = i;

    const float qx = qpts[3 * q + 0];
    const float qy = qpts[3 * q + 1];
    const float qz = qpts[3 * q + 2];
    const float q2 = __fadd_rn(__fadd_rn(__fmul_rn(qx, qx), __fmul_rn(qy, qy)),
                               __fmul_rn(qz, qz));

    // candidate x-window (1 extra guard bin each side)
    const int lo = max(bin_of(qx - RWIN) - 1, 0);
    const int hi = min(bin_of(qx + RWIN) + 1, NBINS - 1);
    const int pbeg = g_start[qb * (NBINS + 1) + lo];
    const int pend = g_start[qb * (NBINS + 1) + hi + 1];

    float ld[FRNQ_LIMIT];
    int   li[FRNQ_LIMIT];
    int   n = 0;

    for (int k = pbeg + lane; k < pend; k += 32) {
        float4 p  = g_pts4[k];
        float dot = __fmaf_rn(qz, p.z, __fmaf_rn(qy, p.y, __fmul_rn(qx, p.x)));
        float s   = __fadd_rn(q2, p.w);
        float d2  = __fmaf_rn(dot, -2.0f, s);
        if (d2 <= R2)
            frnq_insert(fmaxf(d2, 0.0f), g_pidx[k], ld, li, n);
    }

    // warp merge: min-reduce + ballot winner, early exit, tie-break by idx
    int   pos = 0;
    float hd  = (n > 0) ? ld[0] : INF;
    int   hi2 = (n > 0) ? li[0] : 0x7fffffff;
    float rd  = INF;
    int   ri  = -1;

    for (int r = 0; r < FRNQ_LIMIT; ++r) {
        float bd = hd;
        #pragma unroll
        for (int off = 16; off > 0; off >>= 1)
            bd = fminf(bd, __shfl_xor_sync(0xffffffffu, bd, off));
        if (bd == INF) break;

        unsigned m  = __ballot_sync(0xffffffffu, hd == bd);
        int      wl = __ffs(m) - 1;
        if (__popc(m) > 1) {
            int myi = (hd == bd) ? hi2 : 0x7fffffff;
            int mi  = myi;
            #pragma unroll
            for (int off = 16; off > 0; off >>= 1)
                mi = min(mi, __shfl_xor_sync(0xffffffffu, mi, off));
            m  = __ballot_sync(0xffffffffu, myi == mi);
            wl = __ffs(m) - 1;
        }
        int wi = __shfl_sync(0xffffffffu, hi2, wl);
        if (r == lane) { rd = bd; ri = wi; }
        if (lane == wl) {
            ++pos;
            if (pos < n) { hd = ld[pos]; hi2 = li[pos]; }
            else         { hd = INF;     hi2 = 0x7fffffff; }
        }
    }

    const size_t o   = (size_t)q * FRNQ_LIMIT + lane;
    const bool   val = (rd < 1e29f);
    out_idx[o]  = val ? (float)ri : -1.0f;
    out_dist[o] = val ? sqrtf(fmaxf(rd, 1e-12f)) : 0.0f;
}

// ---------------------------------------------------------------------------
extern "C" void kernel_launch(void* const* d_in, const int* in_sizes, int n_in,
                              void* d_out, int out_size)
{
    const float* points     = (const float*)d_in[0];
    const int*   row_splits = (const int*)  d_in[1];
    const float* qpts       = (const float*)d_in[2];
    const int*   q_splits   = (const int*)  d_in[3];

    const int n_qs = in_sizes[3];
    const int B    = in_sizes[1] - 1;
    const int Q    = in_sizes[2] / 3;

    float* out_idx  = (float*)d_out;
    float* out_dist = out_idx + (size_t)Q * FRNQ_LIMIT;

    frnq_bin_kernel<<<B, 512>>>(points, row_splits);

    const int qblocks = (Q + FRNQ_QWARPS - 1) / FRNQ_QWARPS;
    frnq_query_kernel<<<qblocks, FRNQ_QTHREADS>>>(qpts, q_splits, n_qs,
                                                  Q, out_idx, out_dist);
}

// round 8
// speedup vs baseline: 1.8257x; 1.1305x over previous
#include <cuda_runtime.h>
#include <math.h>

// FixedRadiusNeighborQuery — 2-D (x,y)-binned candidate pruning.
//
// Kernel 1 (one block per batch): histogram points into 64x64 bins over
// [-6.5,6.5]^2, block exclusive-scan, scatter into global scratch as
// float4{x,y,z,p2} + orig idx, bin-major sorted (by*64+bx).
// Kernel 2 (one warp per query): for each y-bin row intersecting
// [qy-0.302, qy+0.302], scan the contiguous x-segment intersecting
// [qx-0.302, qx+0.302]. Window is a provable superset of the reference's
// accepted set: bin_of is monotone, and 0.302 has >1e-3 margin over the
// max accepted |dx| (0.30017 incl. fp error of the d2 chain), so no guard
// bins are needed. Every candidate is evaluated with the bit-identical
// reference arithmetic, so the output matches exactly.
//
//   p2 = (x*x + y*y) + z*z
//   dot = fma(qz,pz, fma(qy,py, qx*px))
//   d2  = fma(dot, -2, q2+p2)
//   valid = d2 <= 0.09f ; dist = sqrtf(max(max(d2,0),1e-12))

#define FRNQ_LIMIT 32
#define NX 64
#define NY 64
#define NBINS2 (NX * NY)
#define MAXN  65536
#define MAXB  16
#define XMIN  (-6.5f)
#define INVW  (NX / 13.0f)
#define RWIN  0.302f

__device__ float4 g_pts4[MAXN];
__device__ int    g_pidx[MAXN];
__device__ int    g_start[MAXB * (NBINS2 + 1)];

__device__ __forceinline__ int bin1(float v) {
    int b = (int)floorf((v - XMIN) * INVW);
    return min(max(b, 0), NX - 1);
}

// ---------------- Kernel 1: 2-D bin + scatter (grid = B, block = 512) ------
#define BK_T 512
#define BK_V (NBINS2 / BK_T)   // 8 bins per thread in the scan

__global__ __launch_bounds__(BK_T)
void frnq_bin_kernel(const float* __restrict__ points,
                     const int*   __restrict__ row_splits)
{
    __shared__ int hist[NBINS2];
    __shared__ int cur[NBINS2];
    __shared__ int wsum[BK_T / 32];

    const int b    = blockIdx.x;
    const int ps   = row_splits[b];
    const int pe   = row_splits[b + 1];
    const int tid  = threadIdx.x;
    const int lane = tid & 31;
    const int wid  = tid >> 5;

    for (int i = tid; i < NBINS2; i += BK_T) hist[i] = 0;
    __syncthreads();

    for (int i = ps + tid; i < pe; i += BK_T) {
        int bx = bin1(points[3 * i + 0]);
        int by = bin1(points[3 * i + 1]);
        atomicAdd(&hist[by * NX + bx], 1);
    }
    __syncthreads();

    // exclusive scan of 4096 counts: 8 sequential per thread + block scan
    const int base = tid * BK_V;
    int loc[BK_V];
    int s = 0;
    #pragma unroll
    for (int v = 0; v < BK_V; ++v) { loc[v] = s; s += hist[base + v]; }

    int inc = s;
    #pragma unroll
    for (int o = 1; o < 32; o <<= 1) {
        int t = __shfl_up_sync(0xffffffffu, inc, o);
        if (lane >= o) inc += t;
    }
    if (lane == 31) wsum[wid] = inc;
    __syncthreads();
    if (wid == 0) {
        int w  = (lane < BK_T / 32) ? wsum[lane] : 0;
        int wi = w;
        #pragma unroll
        for (int o = 1; o < BK_T / 32; o <<= 1) {
            int t = __shfl_up_sync(0xffffffffu, wi, o);
            if (lane >= o) wi += t;
        }
        if (lane < BK_T / 32) wsum[lane] = wi - w;
    }
    __syncthreads();
    const int excl = inc - s + wsum[wid];

    const int gb = b * (NBINS2 + 1);
    #pragma unroll
    for (int v = 0; v < BK_V; ++v) {
        g_start[gb + base + v] = ps + excl + loc[v];
        cur[base + v] = excl + loc[v];
    }
    if (tid == 0) g_start[gb + NBINS2] = pe;
    __syncthreads();

    // scatter (within-bin order nondeterministic; output is order-invariant)
    for (int i = ps + tid; i < pe; i += BK_T) {
        float x = points[3 * i + 0];
        float y = points[3 * i + 1];
        float z = points[3 * i + 2];
        float p2 = __fadd_rn(__fadd_rn(__fmul_rn(x, x), __fmul_rn(y, y)),
                             __fmul_rn(z, z));
        int bn  = bin1(y) * NX + bin1(x);
        int pos = ps + atomicAdd(&cur[bn], 1);
        g_pts4[pos] = make_float4(x, y, z, p2);
        g_pidx[pos] = i;
    }
}

// ---------------- Kernel 2: query (1 warp per query) -----------------------
#define FRNQ_QWARPS 8
#define FRNQ_QTHREADS (FRNQ_QWARPS * 32)

__device__ __forceinline__ void frnq_insert(float d2, int idx,
                                            float* ld, int* li, int& n) {
    if (n < FRNQ_LIMIT || d2 < ld[FRNQ_LIMIT - 1]) {
        int j = (n < FRNQ_LIMIT) ? n : (FRNQ_LIMIT - 1);
        while (j > 0 && ld[j - 1] > d2) {
            ld[j] = ld[j - 1];
            li[j] = li[j - 1];
            --j;
        }
        ld[j] = d2;
        li[j] = idx;
        if (n < FRNQ_LIMIT) ++n;
    }
}

__global__ __launch_bounds__(FRNQ_QTHREADS)
void frnq_query_kernel(const float* __restrict__ qpts,
                       const int*   __restrict__ q_splits, int n_qs,
                       int Q,
                       float* __restrict__ out_idx,
                       float* __restrict__ out_dist)
{
    const int lane = threadIdx.x & 31;
    const int warp = threadIdx.x >> 5;
    const int q    = blockIdx.x * FRNQ_QWARPS + warp;
    if (q >= Q) return;

    const float R2  = 0.09f;
    const float INF = __int_as_float(0x7f800000);

    int qb = 0;
    for (int i = 1; i < n_qs; ++i)
        if (q_splits[i] <= q) qb = i;

    const float qx = qpts[3 * q + 0];
    const float qy = qpts[3 * q + 1];
    const float qz = qpts[3 * q + 2];
    const float q2 = __fadd_rn(__fadd_rn(__fmul_rn(qx, qx), __fmul_rn(qy, qy)),
                               __fmul_rn(qz, qz));

    const int bxlo = bin1(qx - RWIN);
    const int bxhi = bin1(qx + RWIN);
    const int bylo = bin1(qy - RWIN);
    const int byhi = bin1(qy + RWIN);
    const int* st  = g_start + qb * (NBINS2 + 1);

    float ld[FRNQ_LIMIT];
    int   li[FRNQ_LIMIT];
    int   n = 0;

    for (int by = bylo; by <= byhi; ++by) {
        const int beg = st[by * NX + bxlo];
        const int end = st[by * NX + bxhi + 1];
        for (int k = beg + lane; k < end; k += 32) {
            float4 p  = g_pts4[k];
            float dot = __fmaf_rn(qz, p.z, __fmaf_rn(qy, p.y, __fmul_rn(qx, p.x)));
            float s   = __fadd_rn(q2, p.w);
            float d2  = __fmaf_rn(dot, -2.0f, s);
            if (d2 <= R2)                                   // rare (~5%)
                frnq_insert(fmaxf(d2, 0.0f), g_pidx[k], ld, li, n);
        }
    }

    // warp merge: min-reduce + ballot winner, early exit, tie-break by idx
    int   pos = 0;
    float hd  = (n > 0) ? ld[0] : INF;
    int   hi2 = (n > 0) ? li[0] : 0x7fffffff;
    float rd  = INF;
    int   ri  = -1;

    for (int r = 0; r < FRNQ_LIMIT; ++r) {
        float bd = hd;
        #pragma unroll
        for (int off = 16; off > 0; off >>= 1)
            bd = fminf(bd, __shfl_xor_sync(0xffffffffu, bd, off));
        if (bd == INF) break;

        unsigned m  = __ballot_sync(0xffffffffu, hd == bd);
        int      wl = __ffs(m) - 1;
        if (__popc(m) > 1) {
            int myi = (hd == bd) ? hi2 : 0x7fffffff;
            int mi  = myi;
            #pragma unroll
            for (int off = 16; off > 0; off >>= 1)
                mi = min(mi, __shfl_xor_sync(0xffffffffu, mi, off));
            m  = __ballot_sync(0xffffffffu, myi == mi);
            wl = __ffs(m) - 1;
        }
        int wi = __shfl_sync(0xffffffffu, hi2, wl);
        if (r == lane) { rd = bd; ri = wi; }
        if (lane == wl) {
            ++pos;
            if (pos < n) { hd = ld[pos]; hi2 = li[pos]; }
            else         { hd = INF;     hi2 = 0x7fffffff; }
        }
    }

    const size_t o   = (size_t)q * FRNQ_LIMIT + lane;
    const bool   val = (rd < 1e29f);
    out_idx[o]  = val ? (float)ri : -1.0f;
    out_dist[o] = val ? sqrtf(fmaxf(rd, 1e-12f)) : 0.0f;
}

// ---------------------------------------------------------------------------
extern "C" void kernel_launch(void* const* d_in, const int* in_sizes, int n_in,
                              void* d_out, int out_size)
{
    const float* points     = (const float*)d_in[0];
    const int*   row_splits = (const int*)  d_in[1];
    const float* qpts       = (const float*)d_in[2];
    const int*   q_splits   = (const int*)  d_in[3];

    const int n_qs = in_sizes[3];
    const int B    = in_sizes[1] - 1;
    const int Q    = in_sizes[2] / 3;

    float* out_idx  = (float*)d_out;
    float* out_dist = out_idx + (size_t)Q * FRNQ_LIMIT;

    frnq_bin_kernel<<<B, BK_T>>>(points, row_splits);

    const int qblocks = (Q + FRNQ_QWARPS - 1) / FRNQ_QWARPS;
    frnq_query_kernel<<<qblocks, FRNQ_QTHREADS>>>(qpts, q_splits, n_qs,
                                                  Q, out_idx, out_dist);
}